// round 9
// baseline (speedup 1.0000x reference)
#include <cuda_runtime.h>
#include <cuda_bf16.h>
#include <math.h>

#define BNF 0.9999950000374997f
#define BN2F 0.9999900000999990f
#define ATT_SCALE 0.40824829046386301637f

// ---- scratch ----
__device__ float g_covp[16][8][288];
__device__ float g_cov[16][484];
__device__ float g_tr[16];
__device__ float g_dlog[16][22];
__device__ float g_rfeat[16][48];
__device__ float g_y[16*32*16000];
__device__ float g_p1[16*32*2000];
__device__ float g_featA[16*250*48];
__device__ float g_featF[16*250*48];
__device__ float g_fused[16*251*48];
__device__ float g_qkv[16*251*144];

__device__ __forceinline__ float eluf(float x){ return x > 0.f ? x : expm1f(x); }
__device__ __forceinline__ float geluf(float x){ return 0.5f*x*(1.f+erff(x*0.70710678118654752f)); }

// covariance partial sums: grid(8 chunks,16 b), block 288
__global__ void k_covp(const float* __restrict__ x){
    __shared__ float xs[22*253];
    int b = blockIdx.y, ch = blockIdx.x, tid = threadIdx.x;
    int i=0,j=0;
    if (tid < 253){ int p=tid; while (p >= 22-i){ p -= 22-i; i++; } j = i+p; }
    int c = tid - 253;
    float acc = 0.f;
    for (int tile = 0; tile < 8; tile++){
        int t0 = ch*2000 + tile*250;
        for (int idx = tid; idx < 22*250; idx += 288){
            int cc = idx/250, t = idx%250;
            xs[cc*253+t] = x[(b*22+cc)*16000 + t0 + t];
        }
        __syncthreads();
        if (tid < 253){
            const float* xi = xs + i*253;
            const float* xj = xs + j*253;
            #pragma unroll 5
            for (int t = 0; t < 250; t++) acc += xi[t]*xj[t];
        } else if (tid < 275){
            const float* xc = xs + c*253;
            #pragma unroll 5
            for (int t = 0; t < 250; t++) acc += xc[t];
        }
        __syncthreads();
    }
    if (tid < 275) g_covp[b][ch][tid] = acc;
}

// grid 16, block 288
__global__ void k_covred(){
    __shared__ float ssm[22];
    __shared__ float dsm[22];
    int b = blockIdx.x, tid = threadIdx.x;
    float s = 0.f;
    if (tid < 275){
        #pragma unroll
        for (int c = 0; c < 8; c++) s += g_covp[b][c][tid];
    }
    if (tid >= 253 && tid < 275) ssm[tid-253] = s;
    __syncthreads();
    if (tid < 253){
        int i=0,p=tid; while (p >= 22-i){ p -= 22-i; i++; } int j = i+p;
        float cov = (s - ssm[i]*ssm[j]*(1.f/16000.f)) * (1.f/15999.f);
        if (i == j){ cov += 1e-5f; dsm[i] = cov; }
        g_cov[b][i*22+j] = cov;
        g_cov[b][j*22+i] = cov;
    }
    __syncthreads();
    if (tid == 0){ float tr=0.f; for (int k=0;k<22;k++) tr += dsm[k]; g_tr[b]=tr; }
}

// 1 block 512: ridge + cholesky(warp/batch) + diag*log(diag)
__global__ void k_chol(){
    __shared__ float A[16*484];
    __shared__ float trm;
    int tid = threadIdx.x;
    if (tid == 0){ float s=0.f; for (int b=0;b<16;b++) s += g_tr[b]; trm = s*(0.001f/16.f); }
    __syncthreads();
    int w = tid >> 5, lane = tid & 31;
    float* a = A + w*484;
    for (int idx = lane; idx < 484; idx += 32) a[idx] = g_cov[w][idx];
    __syncwarp();
    if (lane < 22) a[lane*22+lane] += trm;
    __syncwarp();
    for (int jj = 0; jj < 22; jj++){
        float dj = 0.f;
        if (lane == jj){ dj = sqrtf(a[jj*22+jj]); a[jj*22+jj] = dj; }
        dj = __shfl_sync(0xffffffffu, dj, jj);
        if (lane > jj && lane < 22) a[lane*22+jj] /= dj;
        __syncwarp();
        if (lane > jj && lane < 22){
            float lij = a[lane*22+jj];
            for (int k = jj+1; k <= lane; k++) a[lane*22+k] -= lij * a[k*22+jj];
        }
        __syncwarp();
    }
    if (lane < 22){
        float d = a[lane*22+lane];
        g_dlog[w][lane] = d * logf(fmaxf(d, 1e-10f));
    }
}

// riem MLP (sparse: only 22 diag rows of flat are nonzero). grid 16, block 256
__global__ void k_riem(const float* __restrict__ w1, const float* __restrict__ b1,
                       const float* __restrict__ w2, const float* __restrict__ b2){
    __shared__ float dl[22];
    __shared__ float hs[256];
    int b = blockIdx.x, tid = threadIdx.x;
    if (tid < 22) dl[tid] = g_dlog[b][tid];
    __syncthreads();
    float acc = b1[tid];
    #pragma unroll
    for (int i = 0; i < 22; i++){
        int pos = i*22 - (i*(i-1))/2;
        acc += dl[i]*w1[pos*256 + tid];
    }
    hs[tid] = eluf(acc);
    __syncthreads();
    if (tid < 48){
        float a2 = b2[tid];
        #pragma unroll 8
        for (int k = 0; k < 256; k++) a2 += hs[k]*w2[k*48+tid];
        g_rfeat[b][tid] = a2;
    }
}

// y[b,oc,t] = sum_ch dw1w[oc,ch]*x[b,ch,t]. grid(63,16), block 256
__global__ void k_y(const float* __restrict__ x, const float* __restrict__ dw1w){
    __shared__ float xs[22*260];
    __shared__ float wsm[32*22];
    int b = blockIdx.y, tid = threadIdx.x;
    int t0 = blockIdx.x*256;
    int tg = t0 + tid;
    for (int ch = 0; ch < 22; ch++)
        xs[ch*260+tid] = (tg < 16000) ? x[(b*22+ch)*16000 + tg] : 0.f;
    for (int idx = tid; idx < 704; idx += 256) wsm[idx] = dw1w[idx];   // FIXED: full load
    __syncthreads();
    if (tg >= 16000) return;
    float xv[22];
    #pragma unroll
    for (int ch = 0; ch < 22; ch++) xv[ch] = xs[ch*260+tid];
    #pragma unroll 4
    for (int oc = 0; oc < 32; oc++){
        float a = 0.f;
        #pragma unroll
        for (int ch = 0; ch < 22; ch++) a += wsm[oc*22+ch]*xv[ch];
        g_y[(b*32+oc)*16000 + tg] = a;
    }
}

// 64-tap FIR + BN^2 + elu + pool8 -> p1. grid(63,16), block 256
__global__ void k_conv1(const float* __restrict__ c1w){
    __shared__ float ys[32*321];
    __shared__ float cws[16*65];
    int b = blockIdx.y, tid = threadIdx.x;
    int u0 = blockIdx.x*32;
    int T0 = u0*8;
    for (int idx = tid; idx < 32*320; idx += 256){
        int oc = idx/320, m = idx%320;
        int tp = T0 - 32 + m;
        ys[oc*321+m] = (tp >= 0 && tp < 16000) ? g_y[(b*32+oc)*16000 + tp] : 0.f;
    }
    for (int idx = tid; idx < 1024; idx += 256){
        int ic = idx >> 6, k = idx & 63;
        cws[ic*65+k] = c1w[idx];
    }
    __syncthreads();
    int oc = tid & 31, grp = tid >> 5;
    const float* yrow = ys + oc*321;
    const float* cw = cws + (oc>>1)*65;
    #pragma unroll
    for (int ii = 0; ii < 4; ii++){
        int ul = grp*4 + ii;
        int u = u0 + ul;
        int base = 8*ul;
        float acc[8], yr[8];
        #pragma unroll
        for (int s = 0; s < 8; s++){ acc[s]=0.f; yr[s]=yrow[base+s]; }
        #pragma unroll
        for (int k = 0; k < 64; k++){
            float w = cw[k];
            #pragma unroll
            for (int s = 0; s < 8; s++) acc[s] += w*yr[s];
            #pragma unroll
            for (int m = 0; m < 7; m++) yr[m] = yr[m+1];
            yr[7] = yrow[base + k + 8];
        }
        if (u < 2000){
            float p = 0.f;
            #pragma unroll
            for (int s = 0; s < 8; s++) p += eluf(BN2F*acc[s]);
            g_p1[(b*32+oc)*2000 + u] = p*0.125f;
        }
    }
}

// dw2(16tap,pad8)*BN -> pw(32->48)*BN -> elu -> pool8 -> featA. grid(16,16), block 256
__global__ void k_c2(const float* __restrict__ dw2w, const float* __restrict__ pww){
    __shared__ float p1s[32*145];
    __shared__ float qs[32*129];
    __shared__ float pwT[32*49];
    __shared__ float dwt[16*33];
    int b = blockIdx.y, tid = threadIdx.x;
    int u0 = blockIdx.x*16;
    int T0 = u0*8;
    for (int idx = tid; idx < 32*144; idx += 256){
        int oc = idx/144, m = idx%144;
        int t = T0 - 8 + m;
        p1s[oc*145+m] = (t >= 0 && t < 2000) ? g_p1[(b*32+oc)*2000 + t] : 0.f;
    }
    for (int idx = tid; idx < 1536; idx += 256){
        int co = idx/32, ci = idx%32;
        pwT[ci*49+co] = pww[idx];
    }
    for (int idx = tid; idx < 512; idx += 256){                       // FIXED: full load
        int oc = idx/16, k = idx%16;
        dwt[k*33+oc] = dw2w[idx];
    }
    __syncthreads();
    for (int v = tid; v < 32*128; v += 256){
        int oc = v & 31, t = v >> 5;
        float a = 0.f;
        #pragma unroll
        for (int k = 0; k < 16; k++) a += dwt[k*33+oc]*p1s[oc*145 + t + k];
        qs[oc*129+t] = a*BNF;
    }
    __syncthreads();
    for (int idx = tid; idx < 48*16; idx += 256){
        int co = idx % 48, ul = idx / 48;
        int u = u0 + ul;
        if (u >= 250) continue;
        float p = 0.f;
        #pragma unroll
        for (int s = 0; s < 8; s++){
            float rr = 0.f;
            #pragma unroll 8
            for (int ci = 0; ci < 32; ci++) rr += pwT[ci*49+co]*qs[ci*129 + 8*ul + s];
            p += eluf(BNF*rr);
        }
        g_featA[(b*250+u)*48 + co] = p*0.125f;
    }
}

// temporal conv branch + residual -> featF. grid(4,16), block 256
__global__ void k_tc(const float* __restrict__ tc1w, const float* __restrict__ tc1b,
                     const float* __restrict__ tc2w, const float* __restrict__ tc2b){
    __shared__ float fa[66*48];
    __shared__ float t1s[24*64];
    int b = blockIdx.y, tid = threadIdx.x;
    int u0 = blockIdx.x*64;
    for (int idx = tid; idx < 66*48; idx += 256){
        int r = idx/48, co = idx%48;
        int u = u0 - 1 + r;
        fa[idx] = (u >= 0 && u < 250) ? g_featA[(b*250+u)*48 + co] : 0.f;
    }
    __syncthreads();
    for (int idx = tid; idx < 24*64; idx += 256){
        int g = idx/64, ul = idx%64;
        if (u0 + ul >= 250) continue;
        float a = tc1b[g];
        #pragma unroll
        for (int ci = 0; ci < 2; ci++)
            #pragma unroll
            for (int k = 0; k < 3; k++)
                a += tc1w[(g*2+ci)*3 + k] * fa[(ul+k)*48 + 2*g + ci];
        t1s[g*64+ul] = geluf(BNF*a);
    }
    __syncthreads();
    for (int idx = tid; idx < 48*64; idx += 256){
        int co = idx % 48, ul = idx / 48;
        int u = u0 + ul;
        if (u >= 250) continue;
        float a = tc2b[co];
        #pragma unroll
        for (int g = 0; g < 24; g++) a += tc2w[co*24+g]*t1s[g*64+ul];
        g_featF[(b*250+u)*48 + co] = fa[(ul+1)*48 + co] + a;
    }
}

// fusion proj + pos_enc. grid(251,16), block 48
__global__ void k_fuse(const float* __restrict__ fproj, const float* __restrict__ pe){
    __shared__ float r[48];
    int n = blockIdx.x, b = blockIdx.y, co = threadIdx.x;
    r[co] = (n == 0) ? g_rfeat[b][co] : g_featF[(b*250 + n - 1)*48 + co];
    __syncthreads();
    float a = pe[n*48 + co];
    #pragma unroll 8
    for (int k = 0; k < 48; k++) a += r[k]*fproj[k*48+co];
    g_fused[(b*251+n)*48 + co] = a;
}

// LN1 + qkv. grid 4016, block 144
__global__ void k_lnqkv(int l, const float* __restrict__ qw, const float* __restrict__ qb,
                        const float* __restrict__ g1, const float* __restrict__ b1){
    __shared__ float xr[48];
    __shared__ float hn[48];
    int row = blockIdx.x, tid = threadIdx.x;
    if (tid < 48) xr[tid] = g_fused[row*48+tid];
    __syncthreads();
    float m = 0.f;
    #pragma unroll 8
    for (int k = 0; k < 48; k++) m += xr[k];
    m *= (1.f/48.f);
    float v = 0.f;
    #pragma unroll 8
    for (int k = 0; k < 48; k++){ float d = xr[k]-m; v += d*d; }
    float rinv = rsqrtf(v*(1.f/48.f) + 1e-5f);
    if (tid < 48) hn[tid] = (xr[tid]-m)*rinv*g1[l*48+tid] + b1[l*48+tid];
    __syncthreads();
    float a = qb[l*144 + tid];
    const float* w = qw + l*48*144;
    #pragma unroll 8
    for (int k = 0; k < 48; k++) a += hn[k]*w[k*144 + tid];
    g_qkv[row*144 + tid] = a;
}

// banded attention + out proj + residual. grid(251,16), block 96
__global__ void k_attn(int l, const float* __restrict__ apw, const float* __restrict__ apb){
    __shared__ float sc[8][12];
    __shared__ float os[48];
    __shared__ float qsm[48];
    int n = blockIdx.x, b = blockIdx.y, tid = threadIdx.x;
    int row = b*251 + n;
    int kl = n-5; if (kl < 0) kl = 0;
    int kh = n+5; if (kh > 250) kh = 250;
    int nk = kh - kl + 1;
    if (tid < 48) qsm[tid] = g_qkv[row*144 + tid];
    __syncthreads();
    if (tid < 88){
        int h = tid/11, kk = tid%11;
        if (kk < nk){
            const float* kv = &g_qkv[(b*251+kl+kk)*144 + 48 + h*6];
            float s = 0.f;
            #pragma unroll
            for (int d = 0; d < 6; d++) s += qsm[h*6+d]*kv[d];
            sc[h][kk] = s*ATT_SCALE;
        }
    }
    __syncthreads();
    if (tid < 8){
        float mx = -1e30f;
        for (int kk = 0; kk < nk; kk++) mx = fmaxf(mx, sc[tid][kk]);
        float ss = 0.f;
        for (int kk = 0; kk < nk; kk++){ float e = expf(sc[tid][kk]-mx); sc[tid][kk] = e; ss += e; }
        float inv = 1.f/ss;
        for (int kk = 0; kk < nk; kk++) sc[tid][kk] *= inv;
    }
    __syncthreads();
    if (tid < 48){
        int h = tid/6, d = tid%6;
        float o = 0.f;
        for (int kk = 0; kk < nk; kk++) o += sc[h][kk]*g_qkv[(b*251+kl+kk)*144 + 96 + h*6 + d];
        os[tid] = o;
    }
    __syncthreads();
    if (tid < 48){
        float a = apb[l*48 + tid];
        const float* w = apw + l*48*48;
        #pragma unroll 8
        for (int k = 0; k < 48; k++) a += os[k]*w[k*48 + tid];
        g_fused[row*48 + tid] += a;
    }
}

// LN2 + FFN + residual. grid 4016, block 192
__global__ void k_ffn(int l, const float* __restrict__ w1, const float* __restrict__ b1,
                      const float* __restrict__ w2, const float* __restrict__ b2,
                      const float* __restrict__ g2, const float* __restrict__ bb2){
    __shared__ float xr[48];
    __shared__ float hn[48];
    __shared__ float h1[192];
    int row = blockIdx.x, tid = threadIdx.x;
    if (tid < 48) xr[tid] = g_fused[row*48+tid];
    __syncthreads();
    float m = 0.f;
    #pragma unroll 8
    for (int k = 0; k < 48; k++) m += xr[k];
    m *= (1.f/48.f);
    float v = 0.f;
    #pragma unroll 8
    for (int k = 0; k < 48; k++){ float d = xr[k]-m; v += d*d; }
    float rinv = rsqrtf(v*(1.f/48.f) + 1e-5f);
    if (tid < 48) hn[tid] = (xr[tid]-m)*rinv*g2[l*48+tid] + bb2[l*48+tid];
    __syncthreads();
    {
        float a = b1[l*192 + tid];
        const float* w = w1 + l*48*192;
        #pragma unroll 8
        for (int k = 0; k < 48; k++) a += hn[k]*w[k*192 + tid];
        h1[tid] = geluf(a);
    }
    __syncthreads();
    if (tid < 48){
        float a = b2[l*48 + tid];
        const float* w = w2 + l*192*48;
        #pragma unroll 8
        for (int k = 0; k < 192; k++) a += h1[k]*w[k*48 + tid];
        g_fused[row*48 + tid] = xr[tid] + a;
    }
}

// mean over tokens + LN + classifier. grid 16, block 64
__global__ void k_head(const float* __restrict__ cg, const float* __restrict__ cb,
                       const float* __restrict__ cw, const float* __restrict__ cbias,
                       float* __restrict__ out){
    __shared__ float gm[48];
    int b = blockIdx.x, tid = threadIdx.x;
    if (tid < 48){
        float s = 0.f;
        for (int n = 0; n < 251; n++) s += g_fused[(b*251+n)*48 + tid];
        gm[tid] = s*(1.f/251.f);
    }
    __syncthreads();
    if (tid < 4){
        float m = 0.f;
        #pragma unroll 8
        for (int k = 0; k < 48; k++) m += gm[k];
        m *= (1.f/48.f);
        float v = 0.f;
        #pragma unroll 8
        for (int k = 0; k < 48; k++){ float d = gm[k]-m; v += d*d; }
        float rinv = rsqrtf(v*(1.f/48.f) + 1e-5f);
        float a = cbias[tid];
        #pragma unroll 8
        for (int k = 0; k < 48; k++){
            float gn = (gm[k]-m)*rinv*cg[k] + cb[k];
            a += gn*cw[k*4 + tid];
        }
        out[b*4 + tid] = a;
    }
}

extern "C" void kernel_launch(void* const* d_in, const int* in_sizes, int n_in,
                              void* d_out, int out_size) {
    const float* x      = (const float*)d_in[0];
    const float* rw1    = (const float*)d_in[1];
    const float* rb1    = (const float*)d_in[2];
    const float* rw2    = (const float*)d_in[3];
    const float* rb2    = (const float*)d_in[4];
    const float* c1w    = (const float*)d_in[5];
    const float* dw1w   = (const float*)d_in[6];
    const float* dw2w   = (const float*)d_in[7];
    const float* pww    = (const float*)d_in[8];
    const float* tc1w   = (const float*)d_in[9];
    const float* tc1b   = (const float*)d_in[10];
    const float* tc2w   = (const float*)d_in[11];
    const float* tc2b   = (const float*)d_in[12];
    const float* fproj  = (const float*)d_in[13];
    const float* pe     = (const float*)d_in[14];
    const float* ln1g   = (const float*)d_in[15];
    const float* ln1b   = (const float*)d_in[16];
    const float* qkvw   = (const float*)d_in[17];
    const float* qkvb   = (const float*)d_in[18];
    const float* apw    = (const float*)d_in[19];
    const float* apb    = (const float*)d_in[20];
    const float* ln2g   = (const float*)d_in[21];
    const float* ln2b   = (const float*)d_in[22];
    const float* fw1    = (const float*)d_in[23];
    const float* fb1    = (const float*)d_in[24];
    const float* fw2    = (const float*)d_in[25];
    const float* fb2    = (const float*)d_in[26];
    const float* clsg   = (const float*)d_in[27];
    const float* clsb   = (const float*)d_in[28];
    const float* clsw   = (const float*)d_in[29];
    const float* clsbias= (const float*)d_in[30];
    float* out = (float*)d_out;

    k_covp<<<dim3(8,16), 288>>>(x);
    k_covred<<<16, 288>>>();
    k_chol<<<1, 512>>>();
    k_riem<<<16, 256>>>(rw1, rb1, rw2, rb2);
    k_y<<<dim3(63,16), 256>>>(x, dw1w);
    k_conv1<<<dim3(63,16), 256>>>(c1w);
    k_c2<<<dim3(16,16), 256>>>(dw2w, pww);
    k_tc<<<dim3(4,16), 256>>>(tc1w, tc1b, tc2w, tc2b);
    k_fuse<<<dim3(251,16), 48>>>(fproj, pe);
    for (int l = 0; l < 4; l++){
        k_lnqkv<<<4016, 144>>>(l, qkvw, qkvb, ln1g, ln1b);
        k_attn<<<dim3(251,16), 96>>>(l, apw, apb);
        k_ffn<<<4016, 192>>>(l, fw1, fb1, fw2, fb2, ln2g, ln2b);
    }
    k_head<<<16, 64>>>(clsg, clsb, clsw, clsbias, out);
}

// round 10
// speedup vs baseline: 1.0160x; 1.0160x over previous
#include <cuda_runtime.h>
#include <cuda_bf16.h>
#include <math.h>

#define BNF 0.9999950000374997f
#define BN2F 0.9999900000999990f
#define ATT_SCALE 0.40824829046386301637f

// ---- scratch ----
__device__ float g_covp[16][8][288];
__device__ float g_cov[16][484];
__device__ float g_tr[16];
__device__ float g_dlog[16][22];
__device__ float g_rfeat[16][48];
__device__ float g_y[16*32*16000];
__device__ float g_p1[16*32*2000];
__device__ float g_featA[16*250*48];
__device__ float g_featF[16*250*48];
__device__ float g_fused[16*251*48];
__device__ float g_qkv[16*251*144];

__device__ __forceinline__ float eluf(float x){ return x > 0.f ? x : expm1f(x); }
__device__ __forceinline__ float geluf(float x){ return 0.5f*x*(1.f+erff(x*0.70710678118654752f)); }

// covariance partial sums: grid(8 chunks,16 b), block 288
__global__ void k_covp(const float* __restrict__ x){
    __shared__ float xs[22*253];
    int b = blockIdx.y, ch = blockIdx.x, tid = threadIdx.x;
    int i=0,j=0;
    if (tid < 253){ int p=tid; while (p >= 22-i){ p -= 22-i; i++; } j = i+p; }
    int c = tid - 253;
    float acc = 0.f;
    for (int tile = 0; tile < 8; tile++){
        int t0 = ch*2000 + tile*250;
        for (int idx = tid; idx < 22*250; idx += 288){
            int cc = idx/250, t = idx%250;
            xs[cc*253+t] = x[(b*22+cc)*16000 + t0 + t];
        }
        __syncthreads();
        if (tid < 253){
            const float* xi = xs + i*253;
            const float* xj = xs + j*253;
            #pragma unroll 5
            for (int t = 0; t < 250; t++) acc += xi[t]*xj[t];
        } else if (tid < 275){
            const float* xc = xs + c*253;
            #pragma unroll 5
            for (int t = 0; t < 250; t++) acc += xc[t];
        }
        __syncthreads();
    }
    if (tid < 275) g_covp[b][ch][tid] = acc;
}

// grid 16, block 288
__global__ void k_covred(){
    __shared__ float ssm[22];
    __shared__ float dsm[22];
    int b = blockIdx.x, tid = threadIdx.x;
    float s = 0.f;
    if (tid < 275){
        #pragma unroll
        for (int c = 0; c < 8; c++) s += g_covp[b][c][tid];
    }
    if (tid >= 253 && tid < 275) ssm[tid-253] = s;
    __syncthreads();
    if (tid < 253){
        int i=0,p=tid; while (p >= 22-i){ p -= 22-i; i++; } int j = i+p;
        float cov = (s - ssm[i]*ssm[j]*(1.f/16000.f)) * (1.f/15999.f);
        if (i == j){ cov += 1e-5f; dsm[i] = cov; }
        g_cov[b][i*22+j] = cov;
        g_cov[b][j*22+i] = cov;
    }
    __syncthreads();
    if (tid == 0){ float tr=0.f; for (int k=0;k<22;k++) tr += dsm[k]; g_tr[b]=tr; }
}

// 1 block 512: ridge + cholesky(warp/batch) + diag*log(diag)
__global__ void k_chol(){
    __shared__ float A[16*484];
    __shared__ float trm;
    int tid = threadIdx.x;
    if (tid == 0){ float s=0.f; for (int b=0;b<16;b++) s += g_tr[b]; trm = s*(0.001f/16.f); }
    __syncthreads();
    int w = tid >> 5, lane = tid & 31;
    float* a = A + w*484;
    for (int idx = lane; idx < 484; idx += 32) a[idx] = g_cov[w][idx];
    __syncwarp();
    if (lane < 22) a[lane*22+lane] += trm;
    __syncwarp();
    for (int jj = 0; jj < 22; jj++){
        float dj = 0.f;
        if (lane == jj){ dj = sqrtf(a[jj*22+jj]); a[jj*22+jj] = dj; }
        dj = __shfl_sync(0xffffffffu, dj, jj);
        if (lane > jj && lane < 22) a[lane*22+jj] /= dj;
        __syncwarp();
        if (lane > jj && lane < 22){
            float lij = a[lane*22+jj];
            for (int k = jj+1; k <= lane; k++) a[lane*22+k] -= lij * a[k*22+jj];
        }
        __syncwarp();
    }
    if (lane < 22){
        float d = a[lane*22+lane];
        g_dlog[w][lane] = d * logf(fmaxf(d, 1e-10f));
    }
}

// riem MLP (sparse: only 22 diag rows of flat are nonzero). grid 16, block 256
__global__ void k_riem(const float* __restrict__ w1, const float* __restrict__ b1,
                       const float* __restrict__ w2, const float* __restrict__ b2){
    __shared__ float dl[22];
    __shared__ float hs[256];
    int b = blockIdx.x, tid = threadIdx.x;
    if (tid < 22) dl[tid] = g_dlog[b][tid];
    __syncthreads();
    float acc = b1[tid];
    #pragma unroll
    for (int i = 0; i < 22; i++){
        int pos = i*22 - (i*(i-1))/2;
        acc += dl[i]*w1[pos*256 + tid];
    }
    hs[tid] = eluf(acc);
    __syncthreads();
    if (tid < 48){
        float a2 = b2[tid];
        #pragma unroll 8
        for (int k = 0; k < 256; k++) a2 += hs[k]*w2[k*48+tid];
        g_rfeat[b][tid] = a2;
    }
}

// y[b,oc,t] = sum_ch dw1w[oc,ch]*x[b,ch,t]. grid(63,16), block 256
__global__ void k_y(const float* __restrict__ x, const float* __restrict__ dw1w){
    __shared__ float xs[22*260];
    __shared__ float wsm[32*22];
    int b = blockIdx.y, tid = threadIdx.x;
    int t0 = blockIdx.x*256;
    int tg = t0 + tid;
    for (int ch = 0; ch < 22; ch++)
        xs[ch*260+tid] = (tg < 16000) ? x[(b*22+ch)*16000 + tg] : 0.f;
    for (int idx = tid; idx < 704; idx += 256) wsm[idx] = dw1w[idx];   // FIXED: full load
    __syncthreads();
    if (tg >= 16000) return;
    float xv[22];
    #pragma unroll
    for (int ch = 0; ch < 22; ch++) xv[ch] = xs[ch*260+tid];
    #pragma unroll 4
    for (int oc = 0; oc < 32; oc++){
        float a = 0.f;
        #pragma unroll
        for (int ch = 0; ch < 22; ch++) a += wsm[oc*22+ch]*xv[ch];
        g_y[(b*32+oc)*16000 + tg] = a;
    }
}

// 64-tap FIR + BN^2 + elu + pool8 -> p1. grid(63,16), block 256
__global__ void k_conv1(const float* __restrict__ c1w){
    __shared__ float ys[32*321];
    __shared__ float cws[16*65];
    int b = blockIdx.y, tid = threadIdx.x;
    int u0 = blockIdx.x*32;
    int T0 = u0*8;
    for (int idx = tid; idx < 32*320; idx += 256){
        int oc = idx/320, m = idx%320;
        int tp = T0 - 32 + m;
        ys[oc*321+m] = (tp >= 0 && tp < 16000) ? g_y[(b*32+oc)*16000 + tp] : 0.f;
    }
    for (int idx = tid; idx < 1024; idx += 256){
        int ic = idx >> 6, k = idx & 63;
        cws[ic*65+k] = c1w[idx];
    }
    __syncthreads();
    int oc = tid & 31, grp = tid >> 5;
    const float* yrow = ys + oc*321;
    const float* cw = cws + (oc>>1)*65;
    #pragma unroll
    for (int ii = 0; ii < 4; ii++){
        int ul = grp*4 + ii;
        int u = u0 + ul;
        int base = 8*ul;
        float acc[8], yr[8];
        #pragma unroll
        for (int s = 0; s < 8; s++){ acc[s]=0.f; yr[s]=yrow[base+s]; }
        #pragma unroll
        for (int k = 0; k < 64; k++){
            float w = cw[k];
            #pragma unroll
            for (int s = 0; s < 8; s++) acc[s] += w*yr[s];
            #pragma unroll
            for (int m = 0; m < 7; m++) yr[m] = yr[m+1];
            yr[7] = yrow[base + k + 8];
        }
        if (u < 2000){
            float p = 0.f;
            #pragma unroll
            for (int s = 0; s < 8; s++) p += eluf(BN2F*acc[s]);
            g_p1[(b*32+oc)*2000 + u] = p*0.125f;
        }
    }
}

// dw2(16tap,pad8)*BN -> pw(32->48)*BN -> elu -> pool8 -> featA. grid(16,16), block 256
__global__ void k_c2(const float* __restrict__ dw2w, const float* __restrict__ pww){
    __shared__ float p1s[32*145];
    __shared__ float qs[32*129];
    __shared__ float pwT[32*49];
    __shared__ float dwt[16*33];
    int b = blockIdx.y, tid = threadIdx.x;
    int u0 = blockIdx.x*16;
    int T0 = u0*8;
    for (int idx = tid; idx < 32*144; idx += 256){
        int oc = idx/144, m = idx%144;
        int t = T0 - 8 + m;
        p1s[oc*145+m] = (t >= 0 && t < 2000) ? g_p1[(b*32+oc)*2000 + t] : 0.f;
    }
    for (int idx = tid; idx < 1536; idx += 256){
        int co = idx/32, ci = idx%32;
        pwT[ci*49+co] = pww[idx];
    }
    for (int idx = tid; idx < 512; idx += 256){                       // FIXED: full load
        int oc = idx/16, k = idx%16;
        dwt[k*33+oc] = dw2w[idx];
    }
    __syncthreads();
    for (int v = tid; v < 32*128; v += 256){
        int oc = v & 31, t = v >> 5;
        float a = 0.f;
        #pragma unroll
        for (int k = 0; k < 16; k++) a += dwt[k*33+oc]*p1s[oc*145 + t + k];
        qs[oc*129+t] = a*BNF;
    }
    __syncthreads();
    for (int idx = tid; idx < 48*16; idx += 256){
        int co = idx % 48, ul = idx / 48;
        int u = u0 + ul;
        if (u >= 250) continue;
        float p = 0.f;
        #pragma unroll
        for (int s = 0; s < 8; s++){
            float rr = 0.f;
            #pragma unroll 8
            for (int ci = 0; ci < 32; ci++) rr += pwT[ci*49+co]*qs[ci*129 + 8*ul + s];
            p += eluf(BNF*rr);
        }
        g_featA[(b*250+u)*48 + co] = p*0.125f;
    }
}

// temporal conv branch + residual -> featF. grid(4,16), block 256
__global__ void k_tc(const float* __restrict__ tc1w, const float* __restrict__ tc1b,
                     const float* __restrict__ tc2w, const float* __restrict__ tc2b){
    __shared__ float fa[66*48];
    __shared__ float t1s[24*64];
    int b = blockIdx.y, tid = threadIdx.x;
    int u0 = blockIdx.x*64;
    for (int idx = tid; idx < 66*48; idx += 256){
        int r = idx/48, co = idx%48;
        int u = u0 - 1 + r;
        fa[idx] = (u >= 0 && u < 250) ? g_featA[(b*250+u)*48 + co] : 0.f;
    }
    __syncthreads();
    for (int idx = tid; idx < 24*64; idx += 256){
        int g = idx/64, ul = idx%64;
        if (u0 + ul >= 250) continue;
        float a = tc1b[g];
        #pragma unroll
        for (int ci = 0; ci < 2; ci++)
            #pragma unroll
            for (int k = 0; k < 3; k++)
                a += tc1w[(g*2+ci)*3 + k] * fa[(ul+k)*48 + 2*g + ci];
        t1s[g*64+ul] = geluf(BNF*a);
    }
    __syncthreads();
    for (int idx = tid; idx < 48*64; idx += 256){
        int co = idx % 48, ul = idx / 48;
        int u = u0 + ul;
        if (u >= 250) continue;
        float a = tc2b[co];
        #pragma unroll
        for (int g = 0; g < 24; g++) a += tc2w[co*24+g]*t1s[g*64+ul];
        g_featF[(b*250+u)*48 + co] = fa[(ul+1)*48 + co] + a;
    }
}

// fusion proj + pos_enc. grid(251,16), block 48
__global__ void k_fuse(const float* __restrict__ fproj, const float* __restrict__ pe){
    __shared__ float r[48];
    int n = blockIdx.x, b = blockIdx.y, co = threadIdx.x;
    r[co] = (n == 0) ? g_rfeat[b][co] : g_featF[(b*250 + n - 1)*48 + co];
    __syncthreads();
    float a = pe[n*48 + co];
    #pragma unroll 8
    for (int k = 0; k < 48; k++) a += r[k]*fproj[k*48+co];
    g_fused[(b*251+n)*48 + co] = a;
}

// LN1 + qkv. grid 4016, block 144
__global__ void k_lnqkv(int l, const float* __restrict__ qw, const float* __restrict__ qb,
                        const float* __restrict__ g1, const float* __restrict__ b1){
    __shared__ float xr[48];
    __shared__ float hn[48];
    int row = blockIdx.x, tid = threadIdx.x;
    if (tid < 48) xr[tid] = g_fused[row*48+tid];
    __syncthreads();
    float m = 0.f;
    #pragma unroll 8
    for (int k = 0; k < 48; k++) m += xr[k];
    m *= (1.f/48.f);
    float v = 0.f;
    #pragma unroll 8
    for (int k = 0; k < 48; k++){ float d = xr[k]-m; v += d*d; }
    float rinv = rsqrtf(v*(1.f/48.f) + 1e-5f);
    if (tid < 48) hn[tid] = (xr[tid]-m)*rinv*g1[l*48+tid] + b1[l*48+tid];
    __syncthreads();
    float a = qb[l*144 + tid];
    const float* w = qw + l*48*144;
    #pragma unroll 8
    for (int k = 0; k < 48; k++) a += hn[k]*w[k*144 + tid];
    g_qkv[row*144 + tid] = a;
}

// banded attention + out proj + residual. grid(251,16), block 96
__global__ void k_attn(int l, const float* __restrict__ apw, const float* __restrict__ apb){
    __shared__ float sc[8][12];
    __shared__ float os[48];
    __shared__ float qsm[48];
    int n = blockIdx.x, b = blockIdx.y, tid = threadIdx.x;
    int row = b*251 + n;
    int kl = n-5; if (kl < 0) kl = 0;
    int kh = n+5; if (kh > 250) kh = 250;
    int nk = kh - kl + 1;
    if (tid < 48) qsm[tid] = g_qkv[row*144 + tid];
    __syncthreads();
    if (tid < 88){
        int h = tid/11, kk = tid%11;
        if (kk < nk){
            const float* kv = &g_qkv[(b*251+kl+kk)*144 + 48 + h*6];
            float s = 0.f;
            #pragma unroll
            for (int d = 0; d < 6; d++) s += qsm[h*6+d]*kv[d];
            sc[h][kk] = s*ATT_SCALE;
        }
    }
    __syncthreads();
    if (tid < 8){
        float mx = -1e30f;
        for (int kk = 0; kk < nk; kk++) mx = fmaxf(mx, sc[tid][kk]);
        float ss = 0.f;
        for (int kk = 0; kk < nk; kk++){ float e = expf(sc[tid][kk]-mx); sc[tid][kk] = e; ss += e; }
        float inv = 1.f/ss;
        for (int kk = 0; kk < nk; kk++) sc[tid][kk] *= inv;
    }
    __syncthreads();
    if (tid < 48){
        int h = tid/6, d = tid%6;
        float o = 0.f;
        for (int kk = 0; kk < nk; kk++) o += sc[h][kk]*g_qkv[(b*251+kl+kk)*144 + 96 + h*6 + d];
        os[tid] = o;
    }
    __syncthreads();
    if (tid < 48){
        float a = apb[l*48 + tid];
        const float* w = apw + l*48*48;
        #pragma unroll 8
        for (int k = 0; k < 48; k++) a += os[k]*w[k*48 + tid];
        g_fused[row*48 + tid] += a;
    }
}

// LN2 + FFN + residual. grid 4016, block 192
__global__ void k_ffn(int l, const float* __restrict__ w1, const float* __restrict__ b1,
                      const float* __restrict__ w2, const float* __restrict__ b2,
                      const float* __restrict__ g2, const float* __restrict__ bb2){
    __shared__ float xr[48];
    __shared__ float hn[48];
    __shared__ float h1[192];
    int row = blockIdx.x, tid = threadIdx.x;
    if (tid < 48) xr[tid] = g_fused[row*48+tid];
    __syncthreads();
    float m = 0.f;
    #pragma unroll 8
    for (int k = 0; k < 48; k++) m += xr[k];
    m *= (1.f/48.f);
    float v = 0.f;
    #pragma unroll 8
    for (int k = 0; k < 48; k++){ float d = xr[k]-m; v += d*d; }
    float rinv = rsqrtf(v*(1.f/48.f) + 1e-5f);
    if (tid < 48) hn[tid] = (xr[tid]-m)*rinv*g2[l*48+tid] + bb2[l*48+tid];
    __syncthreads();
    {
        float a = b1[l*192 + tid];
        const float* w = w1 + l*48*192;
        #pragma unroll 8
        for (int k = 0; k < 48; k++) a += hn[k]*w[k*192 + tid];
        h1[tid] = geluf(a);
    }
    __syncthreads();
    if (tid < 48){
        float a = b2[l*48 + tid];
        const float* w = w2 + l*192*48;
        #pragma unroll 8
        for (int k = 0; k < 192; k++) a += h1[k]*w[k*48 + tid];
        g_fused[row*48 + tid] = xr[tid] + a;
    }
}

// mean over tokens + LN + classifier. grid 16, block 64
__global__ void k_head(const float* __restrict__ cg, const float* __restrict__ cb,
                       const float* __restrict__ cw, const float* __restrict__ cbias,
                       float* __restrict__ out){
    __shared__ float gm[48];
    int b = blockIdx.x, tid = threadIdx.x;
    if (tid < 48){
        float s = 0.f;
        for (int n = 0; n < 251; n++) s += g_fused[(b*251+n)*48 + tid];
        gm[tid] = s*(1.f/251.f);
    }
    __syncthreads();
    if (tid < 4){
        float m = 0.f;
        #pragma unroll 8
        for (int k = 0; k < 48; k++) m += gm[k];
        m *= (1.f/48.f);
        float v = 0.f;
        #pragma unroll 8
        for (int k = 0; k < 48; k++){ float d = gm[k]-m; v += d*d; }
        float rinv = rsqrtf(v*(1.f/48.f) + 1e-5f);
        float a = cbias[tid];
        #pragma unroll 8
        for (int k = 0; k < 48; k++){
            float gn = (gm[k]-m)*rinv*cg[k] + cb[k];
            a += gn*cw[k*4 + tid];
        }
        out[b*4 + tid] = a;
    }
}

extern "C" void kernel_launch(void* const* d_in, const int* in_sizes, int n_in,
                              void* d_out, int out_size) {
    const float* x      = (const float*)d_in[0];
    const float* rw1    = (const float*)d_in[1];
    const float* rb1    = (const float*)d_in[2];
    const float* rw2    = (const float*)d_in[3];
    const float* rb2    = (const float*)d_in[4];
    const float* c1w    = (const float*)d_in[5];
    const float* dw1w   = (const float*)d_in[6];
    const float* dw2w   = (const float*)d_in[7];
    const float* pww    = (const float*)d_in[8];
    const float* tc1w   = (const float*)d_in[9];
    const float* tc1b   = (const float*)d_in[10];
    const float* tc2w   = (const float*)d_in[11];
    const float* tc2b   = (const float*)d_in[12];
    const float* fproj  = (const float*)d_in[13];
    const float* pe     = (const float*)d_in[14];
    const float* ln1g   = (const float*)d_in[15];
    const float* ln1b   = (const float*)d_in[16];
    const float* qkvw   = (const float*)d_in[17];
    const float* qkvb   = (const float*)d_in[18];
    const float* apw    = (const float*)d_in[19];
    const float* apb    = (const float*)d_in[20];
    const float* ln2g   = (const float*)d_in[21];
    const float* ln2b   = (const float*)d_in[22];
    const float* fw1    = (const float*)d_in[23];
    const float* fb1    = (const float*)d_in[24];
    const float* fw2    = (const float*)d_in[25];
    const float* fb2    = (const float*)d_in[26];
    const float* clsg   = (const float*)d_in[27];
    const float* clsb   = (const float*)d_in[28];
    const float* clsw   = (const float*)d_in[29];
    const float* clsbias= (const float*)d_in[30];
    float* out = (float*)d_out;

    k_covp<<<dim3(8,16), 288>>>(x);
    k_covred<<<16, 288>>>();
    k_chol<<<1, 512>>>();
    k_riem<<<16, 256>>>(rw1, rb1, rw2, rb2);
    k_y<<<dim3(63,16), 256>>>(x, dw1w);
    k_conv1<<<dim3(63,16), 256>>>(c1w);
    k_c2<<<dim3(16,16), 256>>>(dw2w, pww);
    k_tc<<<dim3(4,16), 256>>>(tc1w, tc1b, tc2w, tc2b);
    k_fuse<<<dim3(251,16), 48>>>(fproj, pe);
    for (int l = 0; l < 4; l++){
        k_lnqkv<<<4016, 144>>>(l, qkvw, qkvb, ln1g, ln1b);
        k_attn<<<dim3(251,16), 96>>>(l, apw, apb);
        k_ffn<<<4016, 192>>>(l, fw1, fb1, fw2, fb2, ln2g, ln2b);
    }
    k_head<<<16, 64>>>(clsg, clsb, clsw, clsbias, out);
}

// round 11
// speedup vs baseline: 1.1396x; 1.1216x over previous
#include <cuda_runtime.h>
#include <cuda_bf16.h>
#include <math.h>

#define BNF 0.9999950000374997f
#define BN2F 0.9999900000999990f
#define ATT_SCALE 0.40824829046386301637f

// ---- scratch ----
__device__ float g_covp[16][8][288];
__device__ float g_rfeat[16][48];
__device__ float g_y[16*32*16000];
__device__ float g_p1[16*32*2000];
__device__ float g_featA[16*250*48];
__device__ float g_featF[16*250*48];
__device__ float g_fused[16*251*48];
__device__ float g_qkv[16*251*144];

__device__ __forceinline__ float eluf(float x){ return x > 0.f ? x : expm1f(x); }
__device__ __forceinline__ float geluf(float x){ return 0.5f*x*(1.f+erff(x*0.70710678118654752f)); }

// covariance partial sums: grid(8 chunks,16 b), block 288
__global__ void k_covp(const float* __restrict__ x){
    __shared__ float xs[22*253];
    int b = blockIdx.y, ch = blockIdx.x, tid = threadIdx.x;
    int i=0,j=0;
    if (tid < 253){ int p=tid; while (p >= 22-i){ p -= 22-i; i++; } j = i+p; }
    int c = tid - 253;
    float acc = 0.f;
    for (int tile = 0; tile < 8; tile++){
        int t0 = ch*2000 + tile*250;
        for (int idx = tid; idx < 22*250; idx += 288){
            int cc = idx/250, t = idx%250;
            xs[cc*253+t] = x[(b*22+cc)*16000 + t0 + t];
        }
        __syncthreads();
        if (tid < 253){
            const float* xi = xs + i*253;
            const float* xj = xs + j*253;
            #pragma unroll 5
            for (int t = 0; t < 250; t++) acc += xi[t]*xj[t];
        } else if (tid < 275){
            const float* xc = xs + c*253;
            #pragma unroll 5
            for (int t = 0; t < 250; t++) acc += xc[t];
        }
        __syncthreads();
    }
    if (tid < 275) g_covp[b][ch][tid] = acc;
}

// merged covred + ridge + cholesky + dlog + riem MLP. 1 block, 512 threads (warp = batch)
__global__ void k_spd(const float* __restrict__ rw1, const float* __restrict__ rb1,
                      const float* __restrict__ rw2, const float* __restrict__ rb2){
    __shared__ float A[16*484];
    __shared__ float chs[16][22];
    __shared__ float dlg[16][22];
    __shared__ float trs[16];
    __shared__ float trm;
    int tid = threadIdx.x, w = tid >> 5, lane = tid & 31;
    float* a = A + w*484;
    if (lane < 22){
        float s = 0.f;
        #pragma unroll
        for (int c = 0; c < 8; c++) s += g_covp[w][c][253+lane];
        chs[w][lane] = s;
    }
    __syncwarp();
    for (int p = lane; p < 253; p += 32){
        int i=0,q=p; while (q >= 22-i){ q -= 22-i; i++; } int j = i+q;
        float s = 0.f;
        #pragma unroll
        for (int c = 0; c < 8; c++) s += g_covp[w][c][p];
        float cov = (s - chs[w][i]*chs[w][j]*(1.f/16000.f)) * (1.f/15999.f);
        if (i == j) cov += 1e-5f;
        a[i*22+j] = cov;
        a[j*22+i] = cov;
    }
    __syncwarp();
    if (lane == 0){ float tr=0.f; for (int k=0;k<22;k++) tr += a[k*22+k]; trs[w]=tr; }
    __syncthreads();
    if (tid == 0){ float s=0.f; for (int b=0;b<16;b++) s += trs[b]; trm = s*(0.001f/16.f); }
    __syncthreads();
    if (lane < 22) a[lane*22+lane] += trm;
    __syncwarp();
    for (int jj = 0; jj < 22; jj++){
        float dj = 0.f;
        if (lane == jj){ dj = sqrtf(a[jj*22+jj]); a[jj*22+jj] = dj; }
        dj = __shfl_sync(0xffffffffu, dj, jj);
        if (lane > jj && lane < 22) a[lane*22+jj] /= dj;
        __syncwarp();
        if (lane > jj && lane < 22){
            float lij = a[lane*22+jj];
            for (int k = jj+1; k <= lane; k++) a[lane*22+k] -= lij * a[k*22+jj];
        }
        __syncwarp();
    }
    if (lane < 22){
        float d = a[lane*22+lane];
        dlg[w][lane] = d * logf(fmaxf(d, 1e-10f));
    }
    __syncwarp();
    // riem MLP: hidden(256) per warp, reuse a[] as hidden buffer
    float hreg[8];
    #pragma unroll
    for (int m = 0; m < 8; m++){
        int h = lane + 32*m;
        float acc = rb1[h];
        #pragma unroll
        for (int i = 0; i < 22; i++){
            int pos = i*22 - (i*(i-1))/2;
            acc += dlg[w][i]*rw1[pos*256 + h];
        }
        hreg[m] = eluf(acc);
    }
    __syncwarp();
    #pragma unroll
    for (int m = 0; m < 8; m++) a[lane + 32*m] = hreg[m];
    __syncwarp();
    for (int o = lane; o < 48; o += 32){
        float acc = rb2[o];
        #pragma unroll 8
        for (int k = 0; k < 256; k++) acc += a[k]*rw2[k*48+o];
        g_rfeat[w][o] = acc;
    }
}

// y[b,oc,t] = sum_ch dw1w[oc,ch]*x[b,ch,t]. grid(63,16), block 256
__global__ void k_y(const float* __restrict__ x, const float* __restrict__ dw1w){
    __shared__ float xs[22*260];
    __shared__ float wsm[32*22];
    int b = blockIdx.y, tid = threadIdx.x;
    int t0 = blockIdx.x*256;
    int tg = t0 + tid;
    for (int ch = 0; ch < 22; ch++)
        xs[ch*260+tid] = (tg < 16000) ? x[(b*22+ch)*16000 + tg] : 0.f;
    for (int idx = tid; idx < 704; idx += 256) wsm[idx] = dw1w[idx];
    __syncthreads();
    if (tg >= 16000) return;
    float xv[22];
    #pragma unroll
    for (int ch = 0; ch < 22; ch++) xv[ch] = xs[ch*260+tid];
    #pragma unroll 4
    for (int oc = 0; oc < 32; oc++){
        float a = 0.f;
        #pragma unroll
        for (int ch = 0; ch < 22; ch++) a += wsm[oc*22+ch]*xv[ch];
        g_y[(b*32+oc)*16000 + tg] = a;
    }
}

// 64-tap FIR + BN^2 + elu + pool8 -> p1. grid(63,16), block 256
__global__ void k_conv1(const float* __restrict__ c1w){
    __shared__ float ys[32*321];
    __shared__ float cws[16*65];
    int b = blockIdx.y, tid = threadIdx.x;
    int u0 = blockIdx.x*32;
    int T0 = u0*8;
    for (int idx = tid; idx < 32*320; idx += 256){
        int oc = idx/320, m = idx%320;
        int tp = T0 - 32 + m;
        ys[oc*321+m] = (tp >= 0 && tp < 16000) ? g_y[(b*32+oc)*16000 + tp] : 0.f;
    }
    for (int idx = tid; idx < 1024; idx += 256){
        int ic = idx >> 6, k = idx & 63;
        cws[ic*65+k] = c1w[idx];
    }
    __syncthreads();
    int oc = tid & 31, grp = tid >> 5;
    const float* yrow = ys + oc*321;
    const float* cw = cws + (oc>>1)*65;
    #pragma unroll
    for (int ii = 0; ii < 4; ii++){
        int ul = grp*4 + ii;
        int u = u0 + ul;
        int base = 8*ul;
        float acc[8], yr[8];
        #pragma unroll
        for (int s = 0; s < 8; s++){ acc[s]=0.f; yr[s]=yrow[base+s]; }
        #pragma unroll
        for (int k = 0; k < 64; k++){
            float w = cw[k];
            #pragma unroll
            for (int s = 0; s < 8; s++) acc[s] += w*yr[s];
            #pragma unroll
            for (int m = 0; m < 7; m++) yr[m] = yr[m+1];
            yr[7] = yrow[base + k + 8];
        }
        if (u < 2000){
            float p = 0.f;
            #pragma unroll
            for (int s = 0; s < 8; s++) p += eluf(BN2F*acc[s]);
            g_p1[(b*32+oc)*2000 + u] = p*0.125f;
        }
    }
}

// dw2 -> pw -> elu -> pool8 -> featA. grid(16,16), block 256
__global__ void k_c2(const float* __restrict__ dw2w, const float* __restrict__ pww){
    __shared__ float p1s[32*145];
    __shared__ float qs[32*129];
    __shared__ float pwT[32*49];
    __shared__ float dwt[16*33];
    int b = blockIdx.y, tid = threadIdx.x;
    int u0 = blockIdx.x*16;
    int T0 = u0*8;
    for (int idx = tid; idx < 32*144; idx += 256){
        int oc = idx/144, m = idx%144;
        int t = T0 - 8 + m;
        p1s[oc*145+m] = (t >= 0 && t < 2000) ? g_p1[(b*32+oc)*2000 + t] : 0.f;
    }
    for (int idx = tid; idx < 1536; idx += 256){
        int co = idx/32, ci = idx%32;
        pwT[ci*49+co] = pww[idx];
    }
    for (int idx = tid; idx < 512; idx += 256){
        int oc = idx/16, k = idx%16;
        dwt[k*33+oc] = dw2w[idx];
    }
    __syncthreads();
    for (int v = tid; v < 32*128; v += 256){
        int oc = v & 31, t = v >> 5;
        float a = 0.f;
        #pragma unroll
        for (int k = 0; k < 16; k++) a += dwt[k*33+oc]*p1s[oc*145 + t + k];
        qs[oc*129+t] = a*BNF;
    }
    __syncthreads();
    for (int idx = tid; idx < 48*16; idx += 256){
        int co = idx % 48, ul = idx / 48;
        int u = u0 + ul;
        if (u >= 250) continue;
        float p = 0.f;
        #pragma unroll
        for (int s = 0; s < 8; s++){
            float rr = 0.f;
            #pragma unroll 8
            for (int ci = 0; ci < 32; ci++) rr += pwT[ci*49+co]*qs[ci*129 + 8*ul + s];
            p += eluf(BNF*rr);
        }
        g_featA[(b*250+u)*48 + co] = p*0.125f;
    }
}

// temporal conv branch + residual -> featF. grid(4,16), block 256
__global__ void k_tc(const float* __restrict__ tc1w, const float* __restrict__ tc1b,
                     const float* __restrict__ tc2w, const float* __restrict__ tc2b){
    __shared__ float fa[66*48];
    __shared__ float t1s[24*64];
    int b = blockIdx.y, tid = threadIdx.x;
    int u0 = blockIdx.x*64;
    for (int idx = tid; idx < 66*48; idx += 256){
        int r = idx/48, co = idx%48;
        int u = u0 - 1 + r;
        fa[idx] = (u >= 0 && u < 250) ? g_featA[(b*250+u)*48 + co] : 0.f;
    }
    __syncthreads();
    for (int idx = tid; idx < 24*64; idx += 256){
        int g = idx/64, ul = idx%64;
        if (u0 + ul >= 250) continue;
        float a = tc1b[g];
        #pragma unroll
        for (int ci = 0; ci < 2; ci++)
            #pragma unroll
            for (int k = 0; k < 3; k++)
                a += tc1w[(g*2+ci)*3 + k] * fa[(ul+k)*48 + 2*g + ci];
        t1s[g*64+ul] = geluf(BNF*a);
    }
    __syncthreads();
    for (int idx = tid; idx < 48*64; idx += 256){
        int co = idx % 48, ul = idx / 48;
        int u = u0 + ul;
        if (u >= 250) continue;
        float a = tc2b[co];
        #pragma unroll
        for (int g = 0; g < 24; g++) a += tc2w[co*24+g]*t1s[g*64+ul];
        g_featF[(b*250+u)*48 + co] = fa[(ul+1)*48 + co] + a;
    }
}

// fusion proj + pos_enc. grid(251,16), block 48
__global__ void k_fuse(const float* __restrict__ fproj, const float* __restrict__ pe){
    __shared__ float r[48];
    int n = blockIdx.x, b = blockIdx.y, co = threadIdx.x;
    r[co] = (n == 0) ? g_rfeat[b][co] : g_featF[(b*250 + n - 1)*48 + co];
    __syncthreads();
    float a = pe[n*48 + co];
    #pragma unroll 8
    for (int k = 0; k < 48; k++) a += r[k]*fproj[k*48+co];
    g_fused[(b*251+n)*48 + co] = a;
}

// LN1 + qkv, 16 rows/block, weights in smem. grid 251, block 288
__global__ void k_lnqkv(int l, const float* __restrict__ qw, const float* __restrict__ qb,
                        const float* __restrict__ g1, const float* __restrict__ b1){
    __shared__ float wq[48*144];
    __shared__ float hn[16][48];
    __shared__ float qbs[144];
    int r0 = blockIdx.x*16;
    int tid = threadIdx.x;
    const float* w = qw + l*48*144;
    for (int idx = tid; idx < 6912; idx += 288) wq[idx] = w[idx];
    if (tid < 144) qbs[tid] = qb[l*144 + tid];
    int wd = tid >> 5, lane = tid & 31;
    if (wd < 8){
        #pragma unroll
        for (int s = 0; s < 2; s++){
            int rl = wd*2 + s;
            int row = r0 + rl;
            float v0 = g_fused[row*48 + lane];
            float v1 = (lane < 16) ? g_fused[row*48 + 32 + lane] : 0.f;
            float sum = v0 + v1, sq = v0*v0 + v1*v1;
            #pragma unroll
            for (int o = 16; o; o >>= 1){
                sum += __shfl_xor_sync(0xffffffffu, sum, o);
                sq  += __shfl_xor_sync(0xffffffffu, sq, o);
            }
            float m = sum*(1.f/48.f);
            float rinv = rsqrtf(sq*(1.f/48.f) - m*m + 1e-5f);
            hn[rl][lane] = (v0-m)*rinv*g1[l*48+lane] + b1[l*48+lane];
            if (lane < 16) hn[rl][32+lane] = (v1-m)*rinv*g1[l*48+32+lane] + b1[l*48+32+lane];
        }
    }
    __syncthreads();
    int g = tid/144, col = tid - g*144;
    float acc[8];
    #pragma unroll
    for (int r = 0; r < 8; r++) acc[r] = qbs[col];
    for (int k = 0; k < 48; k++){
        float wv = wq[k*144 + col];
        #pragma unroll
        for (int r = 0; r < 8; r++) acc[r] += hn[g*8+r][k]*wv;
    }
    #pragma unroll
    for (int r = 0; r < 8; r++) g_qkv[(r0 + g*8 + r)*144 + col] = acc[r];
}

// banded attention + out proj + residual, 16 tokens/block. grid(16,16), block 128
__global__ void k_attn(int l, const float* __restrict__ apw, const float* __restrict__ apb){
    __shared__ float qs[26*144];
    __shared__ float wp[48*48];
    __shared__ float sc[16][8][12];
    __shared__ float os[16][48];
    int b = blockIdx.y, tid = threadIdx.x;
    int n0 = blockIdx.x*16;
    int base = n0 - 5;
    for (int idx = tid; idx < 26*144; idx += 128){
        int r = idx/144, c = idx - r*144;
        int n = base + r;
        qs[idx] = (n >= 0 && n < 251) ? g_qkv[(b*251+n)*144 + c] : 0.f;
    }
    const float* w = apw + l*48*48;
    for (int idx = tid; idx < 2304; idx += 128) wp[idx] = w[idx];
    __syncthreads();
    for (int idx = tid; idx < 1408; idx += 128){
        int tl = idx/88, rem = idx - tl*88, h = rem/11, kk = rem - h*11;
        int n = n0 + tl;
        if (n >= 251) continue;
        int kpos = n - 5 + kk;
        if (kpos < 0 || kpos > 250) continue;
        int rq = tl + 5, rk = tl + kk;
        float s = 0.f;
        #pragma unroll
        for (int d = 0; d < 6; d++) s += qs[rq*144 + h*6 + d]*qs[rk*144 + 48 + h*6 + d];
        sc[tl][h][kk] = s*ATT_SCALE;
    }
    __syncthreads();
    {
        int tl = tid >> 3, h = tid & 7;
        int n = n0 + tl;
        if (n < 251){
            int klo = (n - 5 < 0) ? 5 - n : 0;
            int khi = (n + 5 > 250) ? 255 - n : 10;
            float mx = -1e30f;
            for (int kk = klo; kk <= khi; kk++) mx = fmaxf(mx, sc[tl][h][kk]);
            float ss = 0.f;
            for (int kk = klo; kk <= khi; kk++){ float e = __expf(sc[tl][h][kk]-mx); sc[tl][h][kk] = e; ss += e; }
            float inv = 1.f/ss;
            float o[6] = {0,0,0,0,0,0};
            for (int kk = klo; kk <= khi; kk++){
                float p = sc[tl][h][kk]*inv;
                int rk = tl + kk;
                #pragma unroll
                for (int d = 0; d < 6; d++) o[d] += p*qs[rk*144 + 96 + h*6 + d];
            }
            #pragma unroll
            for (int d = 0; d < 6; d++) os[tl][h*6+d] = o[d];
        }
    }
    __syncthreads();
    for (int idx = tid; idx < 768; idx += 128){
        int rl = idx/48, col = idx - rl*48;
        int n = n0 + rl;
        if (n >= 251) continue;
        float acc = apb[l*48 + col];
        #pragma unroll 8
        for (int k = 0; k < 48; k++) acc += os[rl][k]*wp[k*48 + col];
        g_fused[(b*251+n)*48 + col] += acc;
    }
}

// LN2 + FFN + residual, 16 rows/block, both weights in dyn smem. grid 251, block 384
__global__ void k_ffn(int l, const float* __restrict__ fw1, const float* __restrict__ fb1,
                      const float* __restrict__ fw2, const float* __restrict__ fb2,
                      const float* __restrict__ g2, const float* __restrict__ bb2){
    extern __shared__ float dsm[];
    float* w1s = dsm;                 // 9216
    float* w2s = dsm + 9216;          // 9216
    float* hn  = dsm + 18432;         // 768
    float* h1  = dsm + 19200;         // 3072
    float* xs  = dsm + 22272;         // 768   (total 23040 floats = 92160 B)
    int r0 = blockIdx.x*16;
    int tid = threadIdx.x;
    const float* w1p = fw1 + l*48*192;
    const float* w2p = fw2 + l*192*48;
    for (int idx = tid; idx < 9216; idx += 384){ w1s[idx] = w1p[idx]; w2s[idx] = w2p[idx]; }
    int wd = tid >> 5, lane = tid & 31;
    if (wd < 8){
        #pragma unroll
        for (int s = 0; s < 2; s++){
            int rl = wd*2 + s;
            int row = r0 + rl;
            float v0 = g_fused[row*48 + lane];
            float v1 = (lane < 16) ? g_fused[row*48 + 32 + lane] : 0.f;
            float sum = v0 + v1, sq = v0*v0 + v1*v1;
            #pragma unroll
            for (int o = 16; o; o >>= 1){
                sum += __shfl_xor_sync(0xffffffffu, sum, o);
                sq  += __shfl_xor_sync(0xffffffffu, sq, o);
            }
            float m = sum*(1.f/48.f);
            float rinv = rsqrtf(sq*(1.f/48.f) - m*m + 1e-5f);
            xs[rl*48 + lane] = v0;
            hn[rl*48 + lane] = (v0-m)*rinv*g2[l*48+lane] + bb2[l*48+lane];
            if (lane < 16){
                xs[rl*48 + 32 + lane] = v1;
                hn[rl*48 + 32 + lane] = (v1-m)*rinv*g2[l*48+32+lane] + bb2[l*48+32+lane];
            }
        }
    }
    __syncthreads();
    {
        int g = tid/192, col = tid - g*192;
        float acc[8];
        float bv = fb1[l*192 + col];
        #pragma unroll
        for (int r = 0; r < 8; r++) acc[r] = bv;
        for (int k = 0; k < 48; k++){
            float wv = w1s[k*192 + col];
            #pragma unroll
            for (int r = 0; r < 8; r++) acc[r] += hn[(g*8+r)*48 + k]*wv;
        }
        #pragma unroll
        for (int r = 0; r < 8; r++) h1[(g*8+r)*192 + col] = geluf(acc[r]);
    }
    __syncthreads();
    {
        int col = tid % 48, rg = tid/48;  // 8 groups x 2 rows
        float a0 = fb2[l*48 + col], a1 = a0;
        for (int k = 0; k < 192; k++){
            float wv = w2s[k*48 + col];
            a0 += h1[(rg*2  )*192 + k]*wv;
            a1 += h1[(rg*2+1)*192 + k]*wv;
        }
        int row0 = r0 + rg*2;
        g_fused[row0*48 + col]     = xs[(rg*2  )*48 + col] + a0;
        g_fused[(row0+1)*48 + col] = xs[(rg*2+1)*48 + col] + a1;
    }
}

// mean over tokens + LN + classifier. grid 16, block 64
__global__ void k_head(const float* __restrict__ cg, const float* __restrict__ cb,
                       const float* __restrict__ cw, const float* __restrict__ cbias,
                       float* __restrict__ out){
    __shared__ float gm[48];
    int b = blockIdx.x, tid = threadIdx.x;
    if (tid < 48){
        float s = 0.f;
        for (int n = 0; n < 251; n++) s += g_fused[(b*251+n)*48 + tid];
        gm[tid] = s*(1.f/251.f);
    }
    __syncthreads();
    if (tid < 4){
        float m = 0.f;
        #pragma unroll 8
        for (int k = 0; k < 48; k++) m += gm[k];
        m *= (1.f/48.f);
        float v = 0.f;
        #pragma unroll 8
        for (int k = 0; k < 48; k++){ float d = gm[k]-m; v += d*d; }
        float rinv = rsqrtf(v*(1.f/48.f) + 1e-5f);
        float a = cbias[tid];
        #pragma unroll 8
        for (int k = 0; k < 48; k++){
            float gn = (gm[k]-m)*rinv*cg[k] + cb[k];
            a += gn*cw[k*4 + tid];
        }
        out[b*4 + tid] = a;
    }
}

#define FFN_SMEM (23040*4)

extern "C" void kernel_launch(void* const* d_in, const int* in_sizes, int n_in,
                              void* d_out, int out_size) {
    const float* x      = (const float*)d_in[0];
    const float* rw1    = (const float*)d_in[1];
    const float* rb1    = (const float*)d_in[2];
    const float* rw2    = (const float*)d_in[3];
    const float* rb2    = (const float*)d_in[4];
    const float* c1w    = (const float*)d_in[5];
    const float* dw1w   = (const float*)d_in[6];
    const float* dw2w   = (const float*)d_in[7];
    const float* pww    = (const float*)d_in[8];
    const float* tc1w   = (const float*)d_in[9];
    const float* tc1b   = (const float*)d_in[10];
    const float* tc2w   = (const float*)d_in[11];
    const float* tc2b   = (const float*)d_in[12];
    const float* fproj  = (const float*)d_in[13];
    const float* pe     = (const float*)d_in[14];
    const float* ln1g   = (const float*)d_in[15];
    const float* ln1b   = (const float*)d_in[16];
    const float* qkvw   = (const float*)d_in[17];
    const float* qkvb   = (const float*)d_in[18];
    const float* apw    = (const float*)d_in[19];
    const float* apb    = (const float*)d_in[20];
    const float* ln2g   = (const float*)d_in[21];
    const float* ln2b   = (const float*)d_in[22];
    const float* fw1    = (const float*)d_in[23];
    const float* fb1    = (const float*)d_in[24];
    const float* fw2    = (const float*)d_in[25];
    const float* fb2    = (const float*)d_in[26];
    const float* clsg   = (const float*)d_in[27];
    const float* clsb   = (const float*)d_in[28];
    const float* clsw   = (const float*)d_in[29];
    const float* clsbias= (const float*)d_in[30];
    float* out = (float*)d_out;

    static int ffn_attr_set = 0;
    if (!ffn_attr_set){
        cudaFuncSetAttribute(k_ffn, cudaFuncAttributeMaxDynamicSharedMemorySize, FFN_SMEM);
        ffn_attr_set = 1;
    }

    k_covp<<<dim3(8,16), 288>>>(x);
    k_spd<<<1, 512>>>(rw1, rb1, rw2, rb2);
    k_y<<<dim3(63,16), 256>>>(x, dw1w);
    k_conv1<<<dim3(63,16), 256>>>(c1w);
    k_c2<<<dim3(16,16), 256>>>(dw2w, pww);
    k_tc<<<dim3(4,16), 256>>>(tc1w, tc1b, tc2w, tc2b);
    k_fuse<<<dim3(251,16), 48>>>(fproj, pe);
    for (int l = 0; l < 4; l++){
        k_lnqkv<<<251, 288>>>(l, qkvw, qkvb, ln1g, ln1b);
        k_attn<<<dim3(16,16), 128>>>(l, apw, apb);
        k_ffn<<<251, 384, FFN_SMEM>>>(l, fw1, fb1, fw2, fb2, ln2g, ln2b);
    }
    k_head<<<16, 64>>>(clsg, clsb, clsw, clsbias, out);
}

// round 12
// speedup vs baseline: 1.1861x; 1.0408x over previous
#include <cuda_runtime.h>
#include <cuda_bf16.h>
#include <math.h>

#define BNF 0.9999950000374997f
#define BN2F 0.9999900000999990f
#define ATT_SCALE 0.40824829046386301637f

// ---- scratch ----
__device__ float g_covp[16][8][288];
__device__ float g_rfeat[16][48];
__device__ float g_p1[16*32*2000];
__device__ float g_featA[16*250*48];
__device__ float g_featF[16*250*48];
__device__ float g_fused[16*251*48];
__device__ float g_attn[16*251*48];

__device__ __forceinline__ float eluf(float x){ return x > 0.f ? x : (__expf(x) - 1.f); }
__device__ __forceinline__ float geluf(float x){ return 0.5f*x*(1.f+erff(x*0.70710678118654752f)); }

// covariance partial sums: grid(8 chunks,16 b), block 288
__global__ void k_covp(const float* __restrict__ x){
    __shared__ float xs[22*253];
    int b = blockIdx.y, ch = blockIdx.x, tid = threadIdx.x;
    int i=0,j=0;
    if (tid < 253){ int p=tid; while (p >= 22-i){ p -= 22-i; i++; } j = i+p; }
    int c = tid - 253;
    float acc = 0.f;
    for (int tile = 0; tile < 8; tile++){
        int t0 = ch*2000 + tile*250;
        for (int idx = tid; idx < 22*250; idx += 288){
            int cc = idx/250, t = idx%250;
            xs[cc*253+t] = x[(b*22+cc)*16000 + t0 + t];
        }
        __syncthreads();
        if (tid < 253){
            const float* xi = xs + i*253;
            const float* xj = xs + j*253;
            #pragma unroll 5
            for (int t = 0; t < 250; t++) acc += xi[t]*xj[t];
        } else if (tid < 275){
            const float* xc = xs + c*253;
            #pragma unroll 5
            for (int t = 0; t < 250; t++) acc += xc[t];
        }
        __syncthreads();
    }
    if (tid < 275) g_covp[b][ch][tid] = acc;
}

// merged covred + ridge + cholesky + dlog + riem MLP. 1 block, 512 threads (warp = batch)
__global__ void k_spd(const float* __restrict__ rw1, const float* __restrict__ rb1,
                      const float* __restrict__ rw2, const float* __restrict__ rb2){
    __shared__ float A[16*484];
    __shared__ float chs[16][22];
    __shared__ float dlg[16][22];
    __shared__ float trs[16];
    __shared__ float trm;
    int tid = threadIdx.x, w = tid >> 5, lane = tid & 31;
    float* a = A + w*484;
    if (lane < 22){
        float s = 0.f;
        #pragma unroll
        for (int c = 0; c < 8; c++) s += g_covp[w][c][253+lane];
        chs[w][lane] = s;
    }
    __syncwarp();
    for (int p = lane; p < 253; p += 32){
        int i=0,q=p; while (q >= 22-i){ q -= 22-i; i++; } int j = i+q;
        float s = 0.f;
        #pragma unroll
        for (int c = 0; c < 8; c++) s += g_covp[w][c][p];
        float cov = (s - chs[w][i]*chs[w][j]*(1.f/16000.f)) * (1.f/15999.f);
        if (i == j) cov += 1e-5f;
        a[i*22+j] = cov;
        a[j*22+i] = cov;
    }
    __syncwarp();
    if (lane == 0){ float tr=0.f; for (int k=0;k<22;k++) tr += a[k*22+k]; trs[w]=tr; }
    __syncthreads();
    if (tid == 0){ float s=0.f; for (int b=0;b<16;b++) s += trs[b]; trm = s*(0.001f/16.f); }
    __syncthreads();
    if (lane < 22) a[lane*22+lane] += trm;
    __syncwarp();
    for (int jj = 0; jj < 22; jj++){
        float dj = 0.f;
        if (lane == jj){ dj = sqrtf(a[jj*22+jj]); a[jj*22+jj] = dj; }
        dj = __shfl_sync(0xffffffffu, dj, jj);
        if (lane > jj && lane < 22) a[lane*22+jj] /= dj;
        __syncwarp();
        if (lane > jj && lane < 22){
            float lij = a[lane*22+jj];
            for (int k = jj+1; k <= lane; k++) a[lane*22+k] -= lij * a[k*22+jj];
        }
        __syncwarp();
    }
    if (lane < 22){
        float d = a[lane*22+lane];
        dlg[w][lane] = d * logf(fmaxf(d, 1e-10f));
    }
    __syncwarp();
    float hreg[8];
    #pragma unroll
    for (int m = 0; m < 8; m++){
        int h = lane + 32*m;
        float acc = rb1[h];
        #pragma unroll
        for (int i = 0; i < 22; i++){
            int pos = i*22 - (i*(i-1))/2;
            acc += dlg[w][i]*rw1[pos*256 + h];
        }
        hreg[m] = acc > 0.f ? acc : expm1f(acc);
    }
    __syncwarp();
    #pragma unroll
    for (int m = 0; m < 8; m++) a[lane + 32*m] = hreg[m];
    __syncwarp();
    for (int o = lane; o < 48; o += 32){
        float acc = rb2[o];
        #pragma unroll 8
        for (int k = 0; k < 256; k++) acc += a[k]*rw2[k*48+o];
        g_rfeat[w][o] = acc;
    }
}

// fused: channel-mix (dw1 o conv1 commuted) -> 64-tap FIR -> BN^2 -> elu -> pool8 -> p1
// grid(63,16), block 512, dynamic smem
__global__ void __launch_bounds__(512, 2) k_conv1f(const float* __restrict__ x,
                                                   const float* __restrict__ dw1w,
                                                   const float* __restrict__ c1w){
    extern __shared__ float sm[];
    float* xs  = sm;            // 22*321 = 7062
    float* ys  = sm + 7062;     // 32*321 = 10272
    float* wsm = sm + 17334;    // 704
    float* cws = sm + 18038;    // 16*65 = 1040   (total 19078 floats)
    int b = blockIdx.y, tid = threadIdx.x;
    int u0 = blockIdx.x*32;
    int T0 = u0*8;
    for (int idx = tid; idx < 22*320; idx += 512){
        int ch = idx/320, m = idx - ch*320;
        int t = T0 - 32 + m;
        xs[ch*321+m] = (t >= 0 && t < 16000) ? x[(b*22+ch)*16000 + t] : 0.f;
    }
    for (int idx = tid; idx < 704; idx += 512) wsm[idx] = dw1w[idx];
    for (int idx = tid; idx < 1024; idx += 512){
        int ic = idx >> 6, k = idx & 63;
        cws[ic*65+k] = c1w[idx];
    }
    __syncthreads();
    for (int idx = tid; idx < 32*320; idx += 512){
        int oc = idx/320, m = idx - oc*320;
        float a = 0.f;
        #pragma unroll
        for (int ch = 0; ch < 22; ch++) a += wsm[oc*22+ch]*xs[ch*321+m];
        ys[oc*321+m] = a;
    }
    __syncthreads();
    int oc = tid & 31, grp = tid >> 5;   // 16 groups x 2 u
    const float* yrow = ys + oc*321;
    const float* cw = cws + (oc>>1)*65;
    #pragma unroll 1
    for (int s2 = 0; s2 < 2; s2++){
        int ul = grp*2 + s2;
        int u = u0 + ul;
        int base = 8*ul;
        float acc[8], yr[8];
        #pragma unroll
        for (int s = 0; s < 8; s++){ acc[s]=0.f; yr[s]=yrow[base+s]; }
        #pragma unroll 8
        for (int k = 0; k < 64; k++){
            float w = cw[k];
            #pragma unroll
            for (int s = 0; s < 8; s++) acc[s] += w*yr[s];
            #pragma unroll
            for (int m = 0; m < 7; m++) yr[m] = yr[m+1];
            yr[7] = yrow[base + k + 8];
        }
        if (u < 2000){
            float p = 0.f;
            #pragma unroll
            for (int s = 0; s < 8; s++) p += eluf(BN2F*acc[s]);
            g_p1[(b*32+oc)*2000 + u] = p*0.125f;
        }
    }
}

// dw2 -> pw -> elu -> pool8 -> featA. grid(16,16), block 256
__global__ void k_c2(const float* __restrict__ dw2w, const float* __restrict__ pww){
    __shared__ float p1s[32*145];
    __shared__ float qs[32*129];
    __shared__ float pwT[32*49];
    __shared__ float dwt[16*33];
    int b = blockIdx.y, tid = threadIdx.x;
    int u0 = blockIdx.x*16;
    int T0 = u0*8;
    for (int idx = tid; idx < 32*144; idx += 256){
        int oc = idx/144, m = idx%144;
        int t = T0 - 8 + m;
        p1s[oc*145+m] = (t >= 0 && t < 2000) ? g_p1[(b*32+oc)*2000 + t] : 0.f;
    }
    for (int idx = tid; idx < 1536; idx += 256){
        int co = idx/32, ci = idx%32;
        pwT[ci*49+co] = pww[idx];
    }
    for (int idx = tid; idx < 512; idx += 256){
        int oc = idx/16, k = idx%16;
        dwt[k*33+oc] = dw2w[idx];
    }
    __syncthreads();
    for (int v = tid; v < 32*128; v += 256){
        int oc = v & 31, t = v >> 5;
        float a = 0.f;
        #pragma unroll
        for (int k = 0; k < 16; k++) a += dwt[k*33+oc]*p1s[oc*145 + t + k];
        qs[oc*129+t] = a*BNF;
    }
    __syncthreads();
    for (int idx = tid; idx < 48*16; idx += 256){
        int co = idx % 48, ul = idx / 48;
        int u = u0 + ul;
        if (u >= 250) continue;
        float p = 0.f;
        #pragma unroll
        for (int s = 0; s < 8; s++){
            float rr = 0.f;
            #pragma unroll 8
            for (int ci = 0; ci < 32; ci++) rr += pwT[ci*49+co]*qs[ci*129 + 8*ul + s];
            p += eluf(BNF*rr);
        }
        g_featA[(b*250+u)*48 + co] = p*0.125f;
    }
}

// temporal conv branch + residual -> featF. grid(4,16), block 256
__global__ void k_tc(const float* __restrict__ tc1w, const float* __restrict__ tc1b,
                     const float* __restrict__ tc2w, const float* __restrict__ tc2b){
    __shared__ float fa[66*48];
    __shared__ float t1s[24*64];
    int b = blockIdx.y, tid = threadIdx.x;
    int u0 = blockIdx.x*64;
    for (int idx = tid; idx < 66*48; idx += 256){
        int r = idx/48, co = idx%48;
        int u = u0 - 1 + r;
        fa[idx] = (u >= 0 && u < 250) ? g_featA[(b*250+u)*48 + co] : 0.f;
    }
    __syncthreads();
    for (int idx = tid; idx < 24*64; idx += 256){
        int g = idx/64, ul = idx%64;
        if (u0 + ul >= 250) continue;
        float a = tc1b[g];
        #pragma unroll
        for (int ci = 0; ci < 2; ci++)
            #pragma unroll
            for (int k = 0; k < 3; k++)
                a += tc1w[(g*2+ci)*3 + k] * fa[(ul+k)*48 + 2*g + ci];
        t1s[g*64+ul] = geluf(BNF*a);
    }
    __syncthreads();
    for (int idx = tid; idx < 48*64; idx += 256){
        int co = idx % 48, ul = idx / 48;
        int u = u0 + ul;
        if (u >= 250) continue;
        float a = tc2b[co];
        #pragma unroll
        for (int g = 0; g < 24; g++) a += tc2w[co*24+g]*t1s[g*64+ul];
        g_featF[(b*250+u)*48 + co] = fa[(ul+1)*48 + co] + a;
    }
}

// fusion proj + pos_enc. grid(251,16), block 48
__global__ void k_fuse(const float* __restrict__ fproj, const float* __restrict__ pe){
    __shared__ float r[48];
    int n = blockIdx.x, b = blockIdx.y, co = threadIdx.x;
    r[co] = (n == 0) ? g_rfeat[b][co] : g_featF[(b*250 + n - 1)*48 + co];
    __syncthreads();
    float a = pe[n*48 + co];
    #pragma unroll 8
    for (int k = 0; k < 48; k++) a += r[k]*fproj[k*48+co];
    g_fused[(b*251+n)*48 + co] = a;
}

// fused LN1 + QKV (with halo) + banded attention + out proj + residual.
// reads g_fused, writes g_attn. grid(16,16), block 256, dynamic smem.
__global__ void k_attnf(int l, const float* __restrict__ qw, const float* __restrict__ qb,
                        const float* __restrict__ g1, const float* __restrict__ b1,
                        const float* __restrict__ apw, const float* __restrict__ apb){
    extern __shared__ float sm[];
    float* wq  = sm;             // 6912
    float* qs  = sm + 6912;      // 26*144 = 3744
    float* xf  = sm + 10656;     // 26*48 = 1248
    float* hn  = sm + 11904;     // 1248
    float* wp  = sm + 13152;     // 2304
    float* os  = sm + 15456;     // 768
    float* sc  = sm + 16224;     // 16*8*12 = 1536
    float* qbs = sm + 17760;     // 144
    float* apbs= sm + 17904;     // 48   (total 17952 floats)
    int b = blockIdx.y, tid = threadIdx.x;
    int n0 = blockIdx.x*16;
    const float* wsrc = qw + l*48*144;
    for (int idx = tid; idx < 6912; idx += 256) wq[idx] = wsrc[idx];
    const float* psrc = apw + l*48*48;
    for (int idx = tid; idx < 2304; idx += 256) wp[idx] = psrc[idx];
    if (tid < 144) qbs[tid] = qb[l*144 + tid];
    if (tid < 48) apbs[tid] = apb[l*48 + tid];
    for (int idx = tid; idx < 26*48; idx += 256){
        int r = idx/48, c = idx - r*48;
        int n = n0 - 5 + r;
        xf[idx] = (n >= 0 && n < 251) ? g_fused[(b*251+n)*48 + c] : 0.f;
    }
    __syncthreads();
    // LN of 26 rows: 8 warps x <=4 rows
    {
        int wd = tid >> 5, lane = tid & 31;
        #pragma unroll
        for (int s = 0; s < 4; s++){
            int rl = wd*4 + s;
            if (rl < 26){
                float v0 = xf[rl*48 + lane];
                float v1 = (lane < 16) ? xf[rl*48 + 32 + lane] : 0.f;
                float sum = v0 + v1, sq = v0*v0 + v1*v1;
                #pragma unroll
                for (int o = 16; o; o >>= 1){
                    sum += __shfl_xor_sync(0xffffffffu, sum, o);
                    sq  += __shfl_xor_sync(0xffffffffu, sq, o);
                }
                float m = sum*(1.f/48.f);
                float rinv = rsqrtf(sq*(1.f/48.f) - m*m + 1e-5f);
                hn[rl*48 + lane] = (v0-m)*rinv*g1[l*48+lane] + b1[l*48+lane];
                if (lane < 16) hn[rl*48 + 32 + lane] = (v1-m)*rinv*g1[l*48+32+lane] + b1[l*48+32+lane];
            }
        }
    }
    __syncthreads();
    // qkv for 26 rows
    for (int idx = tid; idx < 26*144; idx += 256){
        int r = idx/144, col = idx - r*144;
        float acc = qbs[col];
        #pragma unroll 8
        for (int k = 0; k < 48; k++) acc += hn[r*48+k]*wq[k*144 + col];
        qs[idx] = acc;
    }
    __syncthreads();
    // scores
    for (int idx = tid; idx < 1408; idx += 256){
        int tl = idx/88, rem = idx - tl*88, h = rem/11, kk = rem - h*11;
        int n = n0 + tl;
        if (n >= 251) continue;
        int kpos = n - 5 + kk;
        if (kpos < 0 || kpos > 250) continue;
        int rq = tl + 5, rk = tl + kk;
        float s = 0.f;
        #pragma unroll
        for (int d = 0; d < 6; d++) s += qs[rq*144 + h*6 + d]*qs[rk*144 + 48 + h*6 + d];
        sc[(tl*8+h)*12 + kk] = s*ATT_SCALE;
    }
    __syncthreads();
    if (tid < 128){
        int tl = tid >> 3, h = tid & 7;
        int n = n0 + tl;
        if (n < 251){
            int klo = (n - 5 < 0) ? 5 - n : 0;
            int khi = (n + 5 > 250) ? 255 - n : 10;
            float mx = -1e30f;
            for (int kk = klo; kk <= khi; kk++) mx = fmaxf(mx, sc[(tl*8+h)*12+kk]);
            float ss = 0.f;
            for (int kk = klo; kk <= khi; kk++){ float e = __expf(sc[(tl*8+h)*12+kk]-mx); sc[(tl*8+h)*12+kk] = e; ss += e; }
            float inv = 1.f/ss;
            float o[6] = {0,0,0,0,0,0};
            for (int kk = klo; kk <= khi; kk++){
                float p = sc[(tl*8+h)*12+kk]*inv;
                int rk = tl + kk;
                #pragma unroll
                for (int d = 0; d < 6; d++) o[d] += p*qs[rk*144 + 96 + h*6 + d];
            }
            #pragma unroll
            for (int d = 0; d < 6; d++) os[tl*48 + h*6+d] = o[d];
        }
    }
    __syncthreads();
    for (int idx = tid; idx < 768; idx += 256){
        int rl = idx/48, col = idx - rl*48;
        int n = n0 + rl;
        if (n >= 251) continue;
        float acc = apbs[col];
        #pragma unroll 8
        for (int k = 0; k < 48; k++) acc += os[rl*48+k]*wp[k*48 + col];
        g_attn[(b*251+n)*48 + col] = xf[(rl+5)*48 + col] + acc;
    }
}

// LN2 + FFN + residual: reads g_attn, writes g_fused. grid 251, block 384, dyn smem
__global__ void k_ffn(int l, const float* __restrict__ fw1, const float* __restrict__ fb1,
                      const float* __restrict__ fw2, const float* __restrict__ fb2,
                      const float* __restrict__ g2, const float* __restrict__ bb2){
    extern __shared__ float dsm[];
    float* w1s = dsm;                 // 9216
    float* w2s = dsm + 9216;          // 9216
    float* hn  = dsm + 18432;         // 768
    float* h1  = dsm + 19200;         // 3072
    float* xs  = dsm + 22272;         // 768   (total 23040 floats)
    int r0 = blockIdx.x*16;
    int tid = threadIdx.x;
    const float* w1p = fw1 + l*48*192;
    const float* w2p = fw2 + l*192*48;
    for (int idx = tid; idx < 9216; idx += 384){ w1s[idx] = w1p[idx]; w2s[idx] = w2p[idx]; }
    int wd = tid >> 5, lane = tid & 31;
    if (wd < 8){
        #pragma unroll
        for (int s = 0; s < 2; s++){
            int rl = wd*2 + s;
            int row = r0 + rl;
            float v0 = g_attn[row*48 + lane];
            float v1 = (lane < 16) ? g_attn[row*48 + 32 + lane] : 0.f;
            float sum = v0 + v1, sq = v0*v0 + v1*v1;
            #pragma unroll
            for (int o = 16; o; o >>= 1){
                sum += __shfl_xor_sync(0xffffffffu, sum, o);
                sq  += __shfl_xor_sync(0xffffffffu, sq, o);
            }
            float m = sum*(1.f/48.f);
            float rinv = rsqrtf(sq*(1.f/48.f) - m*m + 1e-5f);
            xs[rl*48 + lane] = v0;
            hn[rl*48 + lane] = (v0-m)*rinv*g2[l*48+lane] + bb2[l*48+lane];
            if (lane < 16){
                xs[rl*48 + 32 + lane] = v1;
                hn[rl*48 + 32 + lane] = (v1-m)*rinv*g2[l*48+32+lane] + bb2[l*48+32+lane];
            }
        }
    }
    __syncthreads();
    {
        int g = tid/192, col = tid - g*192;
        float acc[8];
        float bv = fb1[l*192 + col];
        #pragma unroll
        for (int r = 0; r < 8; r++) acc[r] = bv;
        for (int k = 0; k < 48; k++){
            float wv = w1s[k*192 + col];
            #pragma unroll
            for (int r = 0; r < 8; r++) acc[r] += hn[(g*8+r)*48 + k]*wv;
        }
        #pragma unroll
        for (int r = 0; r < 8; r++) h1[(g*8+r)*192 + col] = geluf(acc[r]);
    }
    __syncthreads();
    {
        int col = tid % 48, rg = tid/48;
        float a0 = fb2[l*48 + col], a1 = a0;
        for (int k = 0; k < 192; k++){
            float wv = w2s[k*48 + col];
            a0 += h1[(rg*2  )*192 + k]*wv;
            a1 += h1[(rg*2+1)*192 + k]*wv;
        }
        int row0 = r0 + rg*2;
        g_fused[row0*48 + col]     = xs[(rg*2  )*48 + col] + a0;
        g_fused[(row0+1)*48 + col] = xs[(rg*2+1)*48 + col] + a1;
    }
}

// mean over tokens + LN + classifier. grid 16, block 64
__global__ void k_head(const float* __restrict__ cg, const float* __restrict__ cb,
                       const float* __restrict__ cw, const float* __restrict__ cbias,
                       float* __restrict__ out){
    __shared__ float gm[48];
    int b = blockIdx.x, tid = threadIdx.x;
    if (tid < 48){
        float s = 0.f;
        for (int n = 0; n < 251; n++) s += g_fused[(b*251+n)*48 + tid];
        gm[tid] = s*(1.f/251.f);
    }
    __syncthreads();
    if (tid < 4){
        float m = 0.f;
        #pragma unroll 8
        for (int k = 0; k < 48; k++) m += gm[k];
        m *= (1.f/48.f);
        float v = 0.f;
        #pragma unroll 8
        for (int k = 0; k < 48; k++){ float d = gm[k]-m; v += d*d; }
        float rinv = rsqrtf(v*(1.f/48.f) + 1e-5f);
        float a = cbias[tid];
        #pragma unroll 8
        for (int k = 0; k < 48; k++){
            float gn = (gm[k]-m)*rinv*cg[k] + cb[k];
            a += gn*cw[k*4 + tid];
        }
        out[b*4 + tid] = a;
    }
}

#define CONV1F_SMEM (19078*4)
#define ATTNF_SMEM  (17952*4)
#define FFN_SMEM    (23040*4)

extern "C" void kernel_launch(void* const* d_in, const int* in_sizes, int n_in,
                              void* d_out, int out_size) {
    const float* x      = (const float*)d_in[0];
    const float* rw1    = (const float*)d_in[1];
    const float* rb1    = (const float*)d_in[2];
    const float* rw2    = (const float*)d_in[3];
    const float* rb2    = (const float*)d_in[4];
    const float* c1w    = (const float*)d_in[5];
    const float* dw1w   = (const float*)d_in[6];
    const float* dw2w   = (const float*)d_in[7];
    const float* pww    = (const float*)d_in[8];
    const float* tc1w   = (const float*)d_in[9];
    const float* tc1b   = (const float*)d_in[10];
    const float* tc2w   = (const float*)d_in[11];
    const float* tc2b   = (const float*)d_in[12];
    const float* fproj  = (const float*)d_in[13];
    const float* pe     = (const float*)d_in[14];
    const float* ln1g   = (const float*)d_in[15];
    const float* ln1b   = (const float*)d_in[16];
    const float* qkvw   = (const float*)d_in[17];
    const float* qkvb   = (const float*)d_in[18];
    const float* apw    = (const float*)d_in[19];
    const float* apb    = (const float*)d_in[20];
    const float* ln2g   = (const float*)d_in[21];
    const float* ln2b   = (const float*)d_in[22];
    const float* fw1    = (const float*)d_in[23];
    const float* fb1    = (const float*)d_in[24];
    const float* fw2    = (const float*)d_in[25];
    const float* fb2    = (const float*)d_in[26];
    const float* clsg   = (const float*)d_in[27];
    const float* clsb   = (const float*)d_in[28];
    const float* clsw   = (const float*)d_in[29];
    const float* clsbias= (const float*)d_in[30];
    float* out = (float*)d_out;

    static int attr_set = 0;
    if (!attr_set){
        cudaFuncSetAttribute(k_conv1f, cudaFuncAttributeMaxDynamicSharedMemorySize, CONV1F_SMEM);
        cudaFuncSetAttribute(k_attnf,  cudaFuncAttributeMaxDynamicSharedMemorySize, ATTNF_SMEM);
        cudaFuncSetAttribute(k_ffn,    cudaFuncAttributeMaxDynamicSharedMemorySize, FFN_SMEM);
        attr_set = 1;
    }

    k_covp<<<dim3(8,16), 288>>>(x);
    k_spd<<<1, 512>>>(rw1, rb1, rw2, rb2);
    k_conv1f<<<dim3(63,16), 512, CONV1F_SMEM>>>(x, dw1w, c1w);
    k_c2<<<dim3(16,16), 256>>>(dw2w, pww);
    k_tc<<<dim3(4,16), 256>>>(tc1w, tc1b, tc2w, tc2b);
    k_fuse<<<dim3(251,16), 48>>>(fproj, pe);
    for (int l = 0; l < 4; l++){
        k_attnf<<<dim3(16,16), 256, ATTNF_SMEM>>>(l, qkvw, qkvb, ln1g, ln1b, apw, apb);
        k_ffn<<<251, 384, FFN_SMEM>>>(l, fw1, fb1, fw2, fb2, ln2g, ln2b);
    }
    k_head<<<16, 64>>>(clsg, clsb, clsw, clsbias, out);
}